// round 1
// baseline (speedup 1.0000x reference)
#include <cuda_runtime.h>
#include <math_constants.h>

// Problem dims (fixed by the reference)
#define B_  16
#define L_  2048
#define DH  1280
#define T_  512
#define DG  768
#define P_  256
#define SCALE_ 0.0625f   // 256^-0.5

// Scratch (device globals: allocation-free rule)
__device__ float g_K[B_ * L_ * P_];   // 32 MB  K = H @ Wk^T
__device__ float g_Q[B_ * T_ * P_];   //  8 MB  Q = G @ Wq^T
__device__ float g_S[B_ * T_ * L_];   // 64 MB  logits -> softmax probs

// ---------------------------------------------------------------------------
// Generic tiled fp32 GEMM.
//   C[M,N] = alpha * A[M,K] @ op(B)
//   TRANS_B = true : B is [N,K] row-major (dot over contiguous K; "NT")
//   TRANS_B = false: B is [K,N] row-major ("NN")
// BM=BN=128, BK=8, 256 threads, 8x8 microtile per thread.
// All shapes in this problem divide the tile sizes exactly -> no bounds checks.
// blockIdx.z = batch index with per-operand batch strides.
// ---------------------------------------------------------------------------
template <bool TRANS_B>
__global__ void __launch_bounds__(256, 2)
gemm_f32(const float* __restrict__ A, const float* __restrict__ B,
         float* __restrict__ C,
         int M, int N, int K,
         long sA, long sB, long sC, float alpha)
{
    constexpr int BM = 128, BN = 128, BK = 8;
    __shared__ float As[BK][BM + 4];
    __shared__ float Bs[BK][BN + 4];

    const long bz = blockIdx.z;
    A += bz * sA;
    B += bz * sB;
    C += bz * sC;

    const int m0 = blockIdx.y * BM;
    const int n0 = blockIdx.x * BN;

    const int tid  = threadIdx.x;
    const int arow = tid >> 1;            // 0..127: tile row loaded by this thread
    const int akof = (tid & 1) * 4;       // k offset within BK (two float4 per row)
    const int ty   = tid >> 4;            // 0..15
    const int tx   = tid & 15;            // 0..15

    float acc[8][8];
#pragma unroll
    for (int i = 0; i < 8; i++)
#pragma unroll
        for (int j = 0; j < 8; j++) acc[i][j] = 0.0f;

    for (int k0 = 0; k0 < K; k0 += BK) {
        // Stage A tile (transpose to k-major in smem)
        float4 av = *(const float4*)(A + (long)(m0 + arow) * K + k0 + akof);
        As[akof + 0][arow] = av.x;
        As[akof + 1][arow] = av.y;
        As[akof + 2][arow] = av.z;
        As[akof + 3][arow] = av.w;

        if (TRANS_B) {
            float4 bv = *(const float4*)(B + (long)(n0 + arow) * K + k0 + akof);
            Bs[akof + 0][arow] = bv.x;
            Bs[akof + 1][arow] = bv.y;
            Bs[akof + 2][arow] = bv.z;
            Bs[akof + 3][arow] = bv.w;
        } else {
            const int krow = tid >> 5;         // 0..7
            const int nc   = (tid & 31) * 4;   // 0..124
            float4 bv = *(const float4*)(B + (long)(k0 + krow) * N + n0 + nc);
            Bs[krow][nc + 0] = bv.x;
            Bs[krow][nc + 1] = bv.y;
            Bs[krow][nc + 2] = bv.z;
            Bs[krow][nc + 3] = bv.w;
        }
        __syncthreads();

#pragma unroll
        for (int k = 0; k < BK; k++) {
            float a[8], b[8];
#pragma unroll
            for (int i = 0; i < 8; i++) a[i] = As[k][ty * 8 + i];
#pragma unroll
            for (int j = 0; j < 8; j++) b[j] = Bs[k][tx * 8 + j];
#pragma unroll
            for (int i = 0; i < 8; i++)
#pragma unroll
                for (int j = 0; j < 8; j++)
                    acc[i][j] = fmaf(a[i], b[j], acc[i][j]);
        }
        __syncthreads();
    }

#pragma unroll
    for (int i = 0; i < 8; i++) {
        const int m = m0 + ty * 8 + i;
        float4* crow = (float4*)(C + (long)m * N + n0 + tx * 8);
        float4 v0 = {acc[i][0] * alpha, acc[i][1] * alpha,
                     acc[i][2] * alpha, acc[i][3] * alpha};
        float4 v1 = {acc[i][4] * alpha, acc[i][5] * alpha,
                     acc[i][6] * alpha, acc[i][7] * alpha};
        crow[0] = v0;
        crow[1] = v1;
    }
}

// ---------------------------------------------------------------------------
// Row softmax over L_=2048, one CTA (256 threads) per row, in-place.
// ---------------------------------------------------------------------------
__global__ void __launch_bounds__(256)
softmax_rows(float* __restrict__ S)
{
    float* p = S + (long)blockIdx.x * L_;
    const int tid = threadIdx.x;

    float v[8];
    float m = -CUDART_INF_F;
#pragma unroll
    for (int i = 0; i < 8; i++) {
        v[i] = p[i * 256 + tid];
        m = fmaxf(m, v[i]);
    }

    __shared__ float red[8];
#pragma unroll
    for (int o = 16; o > 0; o >>= 1)
        m = fmaxf(m, __shfl_xor_sync(0xffffffffu, m, o));
    if ((tid & 31) == 0) red[tid >> 5] = m;
    __syncthreads();
    m = red[0];
#pragma unroll
    for (int i = 1; i < 8; i++) m = fmaxf(m, red[i]);

    float s = 0.0f;
#pragma unroll
    for (int i = 0; i < 8; i++) {
        v[i] = __expf(v[i] - m);
        s += v[i];
    }
#pragma unroll
    for (int o = 16; o > 0; o >>= 1)
        s += __shfl_xor_sync(0xffffffffu, s, o);
    __syncthreads();                 // protect red[] reuse (WAR)
    if ((tid & 31) == 0) red[tid >> 5] = s;
    __syncthreads();
    s = red[0];
#pragma unroll
    for (int i = 1; i < 8; i++) s += red[i];

    const float inv = 1.0f / s;
#pragma unroll
    for (int i = 0; i < 8; i++) p[i * 256 + tid] = v[i] * inv;
}

// ---------------------------------------------------------------------------
// Launch: 5 kernels, all on the default stream (graph-capturable, no allocs).
//   1) K = H @ Wk^T          M=B*L=32768, N=256, K=1280   (NT)
//   2) Q = G @ Wq^T          M=B*T= 8192, N=256, K= 768   (NT)
//   3) S = scale * Q @ K^T   per b: M=512, N=2048, K=256  (NT, batched)
//   4) softmax rows of S
//   5) Z = S @ H             per b: M=512, N=1280, K=2048 (NN, batched)
// ---------------------------------------------------------------------------
extern "C" void kernel_launch(void* const* d_in, const int* in_sizes, int n_in,
                              void* d_out, int out_size)
{
    const float* H  = (const float*)d_in[0];  // [B, L, DH]
    const float* G  = (const float*)d_in[1];  // [B, T, DG]
    const float* Wq = (const float*)d_in[2];  // [P, DG]
    const float* Wk = (const float*)d_in[3];  // [P, DH]
    float* Z = (float*)d_out;                 // [B, T, DH]

    float *gK, *gQ, *gS;
    cudaGetSymbolAddress((void**)&gK, g_K);
    cudaGetSymbolAddress((void**)&gQ, g_Q);
    cudaGetSymbolAddress((void**)&gS, g_S);

    dim3 blk(256);

    // 1) K-projection
    {
        dim3 grid(P_ / 128, (B_ * L_) / 128, 1);
        gemm_f32<true><<<grid, blk>>>(H, Wk, gK, B_ * L_, P_, DH, 0, 0, 0, 1.0f);
    }
    // 2) Q-projection
    {
        dim3 grid(P_ / 128, (B_ * T_) / 128, 1);
        gemm_f32<true><<<grid, blk>>>(G, Wq, gQ, B_ * T_, P_, DG, 0, 0, 0, 1.0f);
    }
    // 3) logits S = scale * Q @ K^T  (batched over B)
    {
        dim3 grid(L_ / 128, T_ / 128, B_);
        gemm_f32<true><<<grid, blk>>>(gQ, gK, gS, T_, L_, P_,
                                      (long)T_ * P_, (long)L_ * P_,
                                      (long)T_ * L_, SCALE_);
    }
    // 4) softmax over L per (b,t) row
    {
        softmax_rows<<<B_ * T_, blk>>>(gS);
    }
    // 5) Z = A @ H  (batched over B)
    {
        dim3 grid(DH / 128, T_ / 128, B_);
        gemm_f32<false><<<grid, blk>>>(gS, H, Z, T_, DH, L_,
                                       (long)T_ * L_, (long)L_ * DH,
                                       (long)T_ * DH, 1.0f);
    }
}

// round 3
// speedup vs baseline: 2.5283x; 2.5283x over previous
#include <cuda_runtime.h>
#include <cuda_bf16.h>
#include <math_constants.h>
#include <cstdint>

// Problem dims (fixed by the reference)
#define B_  16
#define L_  2048
#define DH  1280
#define T_  512
#define DG  768
#define P_  256
#define SCALE_ 0.0625f   // 256^-0.5

// Scratch (device globals: allocation-free rule)
__device__ float g_K[B_ * L_ * P_];   // 32 MB  K = H @ Wk^T
__device__ float g_Q[B_ * T_ * P_];   //  8 MB  Q = G @ Wq^T
__device__ float g_S[B_ * T_ * L_];   // 64 MB  logits -> softmax probs

// ---------------------------------------------------------------------------
// bf16-split tensor-core GEMM:  C = alpha * A @ op(B), fp32 in/out.
// Each fp32 value x is split into bf16 hi/lo (x ~= h + l); the product uses
// three MMAs: Ah*Bh + Al*Bh + Ah*Bl  (error ~2^-17, >>1e-3 margin).
//   TRANS_B = true : B is [N,K] row-major ("NT")
//   TRANS_B = false: B is [K,N] row-major ("NN"; transposed while staging)
// BM=BN=128, BK=32, 256 threads = 8 warps (2 x 4), warp tile 64(M) x 32(N).
// All problem dims divide the tiles exactly -> no bounds checks.
// ---------------------------------------------------------------------------
#define BM 128
#define BN 128
#define BK 32
#define SK 40                          // padded smem row stride (bf16 elems)
#define STAGE_A (BM * SK)              // bf16 elems per stage per array
#define STAGE_B (BN * SK)
#define SMEM_ELEMS (8 * BM * SK)       // Ah[2],Al[2],Bh[2],Bl[2]
#define SMEM_BYTES (SMEM_ELEMS * 2)    // 81920 bytes
#define HL_OFF (2 * STAGE_A * 2)       // byte offset hi-array -> lo-array

__device__ __forceinline__ uint32_t smem_a32(const void* p) {
    return (uint32_t)__cvta_generic_to_shared(p);
}

__device__ __forceinline__ void ldm4(uint32_t a, uint32_t& r0, uint32_t& r1,
                                     uint32_t& r2, uint32_t& r3) {
    asm volatile("ldmatrix.sync.aligned.m8n8.x4.shared.b16 {%0,%1,%2,%3}, [%4];\n"
                 : "=r"(r0), "=r"(r1), "=r"(r2), "=r"(r3) : "r"(a));
}

__device__ __forceinline__ void mma16816(float* c, const uint32_t* a,
                                         uint32_t b0, uint32_t b1) {
    asm volatile(
        "mma.sync.aligned.m16n8k16.row.col.f32.bf16.bf16.f32 "
        "{%0,%1,%2,%3}, {%4,%5,%6,%7}, {%8,%9}, {%0,%1,%2,%3};\n"
        : "+f"(c[0]), "+f"(c[1]), "+f"(c[2]), "+f"(c[3])
        : "r"(a[0]), "r"(a[1]), "r"(a[2]), "r"(a[3]), "r"(b0), "r"(b1));
}

// split two fp32 into bf16 hi/lo pairs and store (k, k+1 contiguous)
__device__ __forceinline__ void split_st2(__nv_bfloat16* ph, __nv_bfloat16* pl,
                                          float x0, float x1) {
    __nv_bfloat162 h, l;
    h.x = __float2bfloat16_rn(x0);
    h.y = __float2bfloat16_rn(x1);
    l.x = __float2bfloat16_rn(x0 - __bfloat162float(h.x));
    l.y = __float2bfloat16_rn(x1 - __bfloat162float(h.y));
    *(__nv_bfloat162*)ph = h;
    *(__nv_bfloat162*)pl = l;
}

template <bool TRANS_B>
__device__ __forceinline__ void stage_load(const float* __restrict__ A,
                                           const float* __restrict__ Bg,
                                           int K, int N, int m0, int n0, int kt,
                                           int avc, int arb, int bn_, int bkb,
                                           float4* ra, float4* rbv, float* rbs) {
    const long k0 = (long)kt * BK;
#pragma unroll
    for (int i = 0; i < 4; i++)
        ra[i] = *(const float4*)(A + (long)(m0 + arb + i * 32) * K + k0 + avc);
    if (TRANS_B) {
#pragma unroll
        for (int i = 0; i < 4; i++)
            rbv[i] = *(const float4*)(Bg + (long)(n0 + arb + i * 32) * K + k0 + avc);
    } else {
#pragma unroll
        for (int i = 0; i < 16; i++)
            rbs[i] = Bg[(k0 + bkb + i) * (long)N + n0 + bn_];
    }
}

template <bool TRANS_B>
__device__ __forceinline__ void stage_store(__nv_bfloat16* sAh, __nv_bfloat16* sAl,
                                            __nv_bfloat16* sBh, __nv_bfloat16* sBl,
                                            int buf, int avc, int arb, int bn_, int bkb,
                                            const float4* ra, const float4* rbv,
                                            const float* rbs) {
    __nv_bfloat16* ah = sAh + buf * STAGE_A;
    __nv_bfloat16* al = sAl + buf * STAGE_A;
#pragma unroll
    for (int i = 0; i < 4; i++) {
        const int off = (arb + i * 32) * SK + avc;
        split_st2(ah + off,     al + off,     ra[i].x, ra[i].y);
        split_st2(ah + off + 2, al + off + 2, ra[i].z, ra[i].w);
    }
    __nv_bfloat16* bh = sBh + buf * STAGE_B;
    __nv_bfloat16* bl = sBl + buf * STAGE_B;
    if (TRANS_B) {
#pragma unroll
        for (int i = 0; i < 4; i++) {
            const int off = (arb + i * 32) * SK + avc;
            split_st2(bh + off,     bl + off,     rbv[i].x, rbv[i].y);
            split_st2(bh + off + 2, bl + off + 2, rbv[i].z, rbv[i].w);
        }
    } else {
        const int off = bn_ * SK + bkb;
#pragma unroll
        for (int i = 0; i < 16; i += 2)
            split_st2(bh + off + i, bl + off + i, rbs[i], rbs[i + 1]);
    }
}

template <bool TRANS_B>
__global__ void __launch_bounds__(256)
gemm_bf16x3(const float* __restrict__ A, const float* __restrict__ Bg,
            float* __restrict__ C, int M, int N, int K,
            long sA, long sB, long sC, float alpha)
{
    extern __shared__ __nv_bfloat16 sm[];
    __nv_bfloat16* sAh = sm;                    // [2][BM][SK]
    __nv_bfloat16* sAl = sAh + 2 * STAGE_A;
    __nv_bfloat16* sBh = sAl + 2 * STAGE_A;     // [2][BN][SK]
    __nv_bfloat16* sBl = sBh + 2 * STAGE_B;

    const long bz = blockIdx.z;
    A  += bz * sA;
    Bg += bz * sB;
    C  += bz * sC;
    const int m0 = blockIdx.y * BM;
    const int n0 = blockIdx.x * BN;
    const int tid  = threadIdx.x;
    const int lane = tid & 31;
    const int wid  = tid >> 5;
    const int wm = (wid & 1) * 64;    // warp M offset within tile
    const int wn = (wid >> 1) * 32;   // warp N offset within tile

    // staging indices (A and NT-B: float4 along k; NN-B: scalar along k)
    const int avc = (tid & 7) * 4;    // k offset of float4
    const int arb = tid >> 3;         // row 0..31 (+ i*32)
    const int bn_ = tid & 127;        // NN: n column
    const int bkb = (tid >> 7) * 16;  // NN: k base (0 or 16)

    float acc[4][4][4];
#pragma unroll
    for (int i = 0; i < 4; i++)
#pragma unroll
        for (int j = 0; j < 4; j++)
#pragma unroll
            for (int q = 0; q < 4; q++) acc[i][j][q] = 0.0f;

    float4 ra[4];
    float4 rbv[4];
    float  rbs[16];

    // ldmatrix base addresses (hi arrays; lo = +HL_OFF bytes)
    const uint32_t aBase = smem_a32(sAh) +
        (uint32_t)(((wm + (lane & 15)) * SK + (lane >> 4) * 8) * 2);
    const int bg = lane >> 3, br = lane & 7;
    const uint32_t bBase = smem_a32(sBh) +
        (uint32_t)(((wn + (bg >> 1) * 8 + br) * SK + (bg & 1) * 8) * 2);

    const int nk = K / BK;

    stage_load<TRANS_B>(A, Bg, K, N, m0, n0, 0, avc, arb, bn_, bkb, ra, rbv, rbs);
    stage_store<TRANS_B>(sAh, sAl, sBh, sBl, 0, avc, arb, bn_, bkb, ra, rbv, rbs);
    __syncthreads();

    for (int kt = 0; kt < nk; kt++) {
        const int cur = kt & 1;
        const bool more = (kt + 1 < nk);
        if (more)
            stage_load<TRANS_B>(A, Bg, K, N, m0, n0, kt + 1, avc, arb, bn_, bkb,
                                ra, rbv, rbs);

        // ---- MMA over current stage (two k16 steps) ----
#pragma unroll
        for (int ks = 0; ks < 2; ks++) {
            uint32_t ah[4][4], al[4][4], bh[2][4], bl[2][4];
#pragma unroll
            for (int fm = 0; fm < 4; fm++) {
                const uint32_t ad = aBase + (uint32_t)(cur * (STAGE_A * 2) +
                                                       fm * (16 * SK * 2) + ks * 32);
                ldm4(ad, ah[fm][0], ah[fm][1], ah[fm][2], ah[fm][3]);
                ldm4(ad + HL_OFF, al[fm][0], al[fm][1], al[fm][2], al[fm][3]);
            }
#pragma unroll
            for (int f2 = 0; f2 < 2; f2++) {
                const uint32_t bd = bBase + (uint32_t)(cur * (STAGE_B * 2) +
                                                       f2 * (16 * SK * 2) + ks * 32);
                ldm4(bd, bh[f2][0], bh[f2][1], bh[f2][2], bh[f2][3]);
                ldm4(bd + HL_OFF, bl[f2][0], bl[f2][1], bl[f2][2], bl[f2][3]);
            }
#pragma unroll
            for (int fm = 0; fm < 4; fm++) {
#pragma unroll
                for (int fn = 0; fn < 4; fn++) {
                    const uint32_t b0h = bh[fn >> 1][(fn & 1) * 2];
                    const uint32_t b1h = bh[fn >> 1][(fn & 1) * 2 + 1];
                    const uint32_t b0l = bl[fn >> 1][(fn & 1) * 2];
                    const uint32_t b1l = bl[fn >> 1][(fn & 1) * 2 + 1];
                    mma16816(acc[fm][fn], ah[fm], b0h, b1h);
                    mma16816(acc[fm][fn], al[fm], b0h, b1h);
                    mma16816(acc[fm][fn], ah[fm], b0l, b1l);
                }
            }
        }

        if (more)
            stage_store<TRANS_B>(sAh, sAl, sBh, sBl, 1 - cur, avc, arb, bn_, bkb,
                                 ra, rbv, rbs);
        __syncthreads();
    }

    // ---- epilogue ----
    const int er = lane >> 2, ec = (lane & 3) * 2;
#pragma unroll
    for (int fm = 0; fm < 4; fm++) {
#pragma unroll
        for (int fn = 0; fn < 4; fn++) {
            const int row = m0 + wm + fm * 16 + er;
            const int col = n0 + wn + fn * 8 + ec;
            float2 v0 = {acc[fm][fn][0] * alpha, acc[fm][fn][1] * alpha};
            float2 v1 = {acc[fm][fn][2] * alpha, acc[fm][fn][3] * alpha};
            *(float2*)(C + (long)row * N + col) = v0;
            *(float2*)(C + (long)(row + 8) * N + col) = v1;
        }
    }
}

// ---------------------------------------------------------------------------
// Row softmax over L_=2048, one CTA (256 threads) per row, in-place.
// ---------------------------------------------------------------------------
__global__ void __launch_bounds__(256)
softmax_rows(float* __restrict__ S)
{
    float* p = S + (long)blockIdx.x * L_;
    const int tid = threadIdx.x;

    float v[8];
    float m = -CUDART_INF_F;
#pragma unroll
    for (int i = 0; i < 8; i++) {
        v[i] = p[i * 256 + tid];
        m = fmaxf(m, v[i]);
    }

    __shared__ float red[8];
#pragma unroll
    for (int o = 16; o > 0; o >>= 1)
        m = fmaxf(m, __shfl_xor_sync(0xffffffffu, m, o));
    if ((tid & 31) == 0) red[tid >> 5] = m;
    __syncthreads();
    m = red[0];
#pragma unroll
    for (int i = 1; i < 8; i++) m = fmaxf(m, red[i]);

    float s = 0.0f;
#pragma unroll
    for (int i = 0; i < 8; i++) {
        v[i] = __expf(v[i] - m);
        s += v[i];
    }
#pragma unroll
    for (int o = 16; o > 0; o >>= 1)
        s += __shfl_xor_sync(0xffffffffu, s, o);
    __syncthreads();
    if ((tid & 31) == 0) red[tid >> 5] = s;
    __syncthreads();
    s = red[0];
#pragma unroll
    for (int i = 1; i < 8; i++) s += red[i];

    const float inv = 1.0f / s;
#pragma unroll
    for (int i = 0; i < 8; i++) p[i * 256 + tid] = v[i] * inv;
}

// ---------------------------------------------------------------------------
// Launch: 5 kernels (graph-capturable, allocation-free).
// ---------------------------------------------------------------------------
extern "C" void kernel_launch(void* const* d_in, const int* in_sizes, int n_in,
                              void* d_out, int out_size)
{
    const float* H  = (const float*)d_in[0];  // [B, L, DH]
    const float* G  = (const float*)d_in[1];  // [B, T, DG]
    const float* Wq = (const float*)d_in[2];  // [P, DG]
    const float* Wk = (const float*)d_in[3];  // [P, DH]
    float* Z = (float*)d_out;                 // [B, T, DH]

    float *gK, *gQ, *gS;
    cudaGetSymbolAddress((void**)&gK, g_K);
    cudaGetSymbolAddress((void**)&gQ, g_Q);
    cudaGetSymbolAddress((void**)&gS, g_S);

    cudaFuncSetAttribute(gemm_bf16x3<true>,
                         cudaFuncAttributeMaxDynamicSharedMemorySize, SMEM_BYTES);
    cudaFuncSetAttribute(gemm_bf16x3<false>,
                         cudaFuncAttributeMaxDynamicSharedMemorySize, SMEM_BYTES);

    dim3 blk(256);

    // 1) K = H @ Wk^T   M=32768, N=256, K=1280
    gemm_bf16x3<true><<<dim3(P_ / BN, (B_ * L_) / BM, 1), blk, SMEM_BYTES>>>(
        H, Wk, gK, B_ * L_, P_, DH, 0, 0, 0, 1.0f);

    // 2) Q = G @ Wq^T   M=8192, N=256, K=768
    gemm_bf16x3<true><<<dim3(P_ / BN, (B_ * T_) / BM, 1), blk, SMEM_BYTES>>>(
        G, Wq, gQ, B_ * T_, P_, DG, 0, 0, 0, 1.0f);

    // 3) S = scale * Q @ K^T   per b: M=512, N=2048, K=256
    gemm_bf16x3<true><<<dim3(L_ / BN, T_ / BM, B_), blk, SMEM_BYTES>>>(
        gQ, gK, gS, T_, L_, P_,
        (long)T_ * P_, (long)L_ * P_, (long)T_ * L_, SCALE_);

    // 4) softmax rows
    softmax_rows<<<B_ * T_, blk>>>(gS);

    // 5) Z = A @ H   per b: M=512, N=1280, K=2048
    gemm_bf16x3<false><<<dim3(DH / BN, T_ / BM, B_), blk, SMEM_BYTES>>>(
        gS, H, Z, T_, DH, L_,
        (long)T_ * L_, (long)L_ * DH, (long)T_ * DH, 1.0f);
}

// round 5
// speedup vs baseline: 5.7161x; 2.2609x over previous
#include <cuda_runtime.h>
#include <cuda_fp16.h>
#include <math_constants.h>
#include <cstdint>

// Problem dims (fixed by the reference)
#define B_  16
#define L_  2048
#define DH  1280
#define T_  512
#define DG  768
#define P_  256
#define SCALE_ 0.0625f   // 256^-0.5

typedef __half fp16;

// ---------------- device-global scratch (allocation-free rule) --------------
__device__ __align__(16) fp16 g_Hf [(long)B_ * L_ * DH];   // H  fp16 [b,l,d]
__device__ __align__(16) fp16 g_Htf[(long)B_ * DH * L_];   // H^T fp16 [b,d,l]
__device__ __align__(16) fp16 g_Gf [(long)B_ * T_ * DG];
__device__ __align__(16) fp16 g_Wqf[P_ * DG];
__device__ __align__(16) fp16 g_Wkf[P_ * DH];
__device__ __align__(16) fp16 g_Kf [(long)B_ * L_ * P_];   // K fp16
__device__ __align__(16) fp16 g_Qf [(long)B_ * T_ * P_];   // Q fp16
__device__ __align__(16) float g_S [(long)B_ * T_ * L_];   // logits fp32
__device__ __align__(16) fp16 g_Sf [(long)B_ * T_ * L_];   // probs fp16

// ---------------------------------------------------------------------------
// fp16 tensor-core GEMM (legacy mma.sync path; compute_103-safe):
//   C[M,N] = alpha * A[M,K] @ B^T   with A [M,K], B [N,K], both fp16 K-major.
//   fp32 accumulation.  EPI=0: fp32 C (alpha applied). EPI=1: fp16 C (alpha=1).
// BM=BN=128, BK=64, 256 threads = 8 warps (2M x 4N), warp tile 64(M) x 32(N).
// Double-buffered smem, SK=72-halves padded rows (ldmatrix conflict-free).
// All problem dims divide the tiles exactly -> no bounds checks.
// ---------------------------------------------------------------------------
#define BM 128
#define BN 128
#define BK 64
#define SK 72
#define STAGE_A (BM * SK)                    // halves
#define STAGE_B (BN * SK)
#define BUF_HALVES (STAGE_A + STAGE_B)
#define SMEM_BYTES (2 * BUF_HALVES * 2)      // 73728 B

__device__ __forceinline__ uint32_t smem_a32(const void* p) {
    return (uint32_t)__cvta_generic_to_shared(p);
}

__device__ __forceinline__ void ldm4(uint32_t a, uint32_t& r0, uint32_t& r1,
                                     uint32_t& r2, uint32_t& r3) {
    asm volatile("ldmatrix.sync.aligned.m8n8.x4.shared.b16 {%0,%1,%2,%3}, [%4];\n"
                 : "=r"(r0), "=r"(r1), "=r"(r2), "=r"(r3) : "r"(a));
}

__device__ __forceinline__ void mma16816(float* c, const uint32_t* a,
                                         uint32_t b0, uint32_t b1) {
    asm volatile(
        "mma.sync.aligned.m16n8k16.row.col.f32.f16.f16.f32 "
        "{%0,%1,%2,%3}, {%4,%5,%6,%7}, {%8,%9}, {%0,%1,%2,%3};\n"
        : "+f"(c[0]), "+f"(c[1]), "+f"(c[2]), "+f"(c[3])
        : "r"(a[0]), "r"(a[1]), "r"(a[2]), "r"(a[3]), "r"(b0), "r"(b1));
}

template <int EPI>
__global__ void __launch_bounds__(256)
gemm_fp16(const fp16* __restrict__ A, const fp16* __restrict__ Bm,
          float* __restrict__ Cf, fp16* __restrict__ Ch,
          int K, int N, long sA, long sB, long sC, float alpha)
{
    extern __shared__ fp16 sm[];   // [2][STAGE_A + STAGE_B]

    const long bz = blockIdx.z;
    A  += bz * sA;
    Bm += bz * sB;
    const int m0 = blockIdx.y * BM;
    const int n0 = blockIdx.x * BN;

    const int tid  = threadIdx.x;
    const int lane = tid & 31;
    const int wid  = tid >> 5;
    const int wm = (wid & 1) * 64;    // warp M offset
    const int wn = (wid >> 1) * 32;   // warp N offset

    // staging: each row is 64 halves = 8 uint4 chunks; 8 threads per row
    const int srow = tid >> 3;        // 0..31 (+ i*32)
    const int scc  = (tid & 7) * 8;   // half offset within row

    float acc[4][4][4];
#pragma unroll
    for (int i = 0; i < 4; i++)
#pragma unroll
        for (int j = 0; j < 4; j++)
#pragma unroll
            for (int q = 0; q < 4; q++) acc[i][j][q] = 0.0f;

    uint4 ra[4], rb[4];

    // ldmatrix base addresses (byte offsets within buffer 0)
    const uint32_t smBase = smem_a32(sm);
    const uint32_t aBase = smBase +
        (uint32_t)(((wm + (lane & 15)) * SK + (lane >> 4) * 8) * 2);
    const int bg = lane >> 3, br = lane & 7;
    const uint32_t bBase = smBase + (uint32_t)(STAGE_A * 2) +
        (uint32_t)(((wn + (bg >> 1) * 8 + br) * SK + (bg & 1) * 8) * 2);

    const int nk = K / BK;

    // ---- prologue: stage k-tile 0 into buffer 0 ----
#pragma unroll
    for (int i = 0; i < 4; i++)
        ra[i] = *(const uint4*)(A + (long)(m0 + srow + i * 32) * K + scc);
#pragma unroll
    for (int i = 0; i < 4; i++)
        rb[i] = *(const uint4*)(Bm + (long)(n0 + srow + i * 32) * K + scc);
#pragma unroll
    for (int i = 0; i < 4; i++) {
        *(uint4*)(sm + (srow + i * 32) * SK + scc) = ra[i];
        *(uint4*)(sm + STAGE_A + (srow + i * 32) * SK + scc) = rb[i];
    }
    __syncthreads();

    for (int kt = 0; kt < nk; kt++) {
        const int cur = kt & 1;
        const bool more = (kt + 1 < nk);
        if (more) {
            const long k0 = (long)(kt + 1) * BK;
#pragma unroll
            for (int i = 0; i < 4; i++)
                ra[i] = *(const uint4*)(A + (long)(m0 + srow + i * 32) * K + k0 + scc);
#pragma unroll
            for (int i = 0; i < 4; i++)
                rb[i] = *(const uint4*)(Bm + (long)(n0 + srow + i * 32) * K + k0 + scc);
        }

        const uint32_t bufOff = (uint32_t)(cur * (BUF_HALVES * 2));
#pragma unroll
        for (int ks = 0; ks < 4; ks++) {
            uint32_t af[4][4], bf[2][4];
#pragma unroll
            for (int fm = 0; fm < 4; fm++)
                ldm4(aBase + bufOff + (uint32_t)(fm * (16 * SK * 2) + ks * 32),
                     af[fm][0], af[fm][1], af[fm][2], af[fm][3]);
#pragma unroll
            for (int f2 = 0; f2 < 2; f2++)
                ldm4(bBase + bufOff + (uint32_t)(f2 * (16 * SK * 2) + ks * 32),
                     bf[f2][0], bf[f2][1], bf[f2][2], bf[f2][3]);
#pragma unroll
            for (int fm = 0; fm < 4; fm++)
#pragma unroll
                for (int fn = 0; fn < 4; fn++)
                    mma16816(acc[fm][fn], af[fm],
                             bf[fn >> 1][(fn & 1) * 2],
                             bf[fn >> 1][(fn & 1) * 2 + 1]);
        }

        if (more) {
            fp16* dst = sm + (1 - cur) * BUF_HALVES;
#pragma unroll
            for (int i = 0; i < 4; i++) {
                *(uint4*)(dst + (srow + i * 32) * SK + scc) = ra[i];
                *(uint4*)(dst + STAGE_A + (srow + i * 32) * SK + scc) = rb[i];
            }
        }
        __syncthreads();
    }

    // ---- epilogue ----
    const int er = lane >> 2, ec = (lane & 3) * 2;
    if (EPI == 0) Cf += bz * sC; else Ch += bz * sC;
#pragma unroll
    for (int fm = 0; fm < 4; fm++) {
#pragma unroll
        for (int fn = 0; fn < 4; fn++) {
            const int row = m0 + wm + fm * 16 + er;
            const int col = n0 + wn + fn * 8 + ec;
            if (EPI == 0) {
                float2 v0 = {acc[fm][fn][0] * alpha, acc[fm][fn][1] * alpha};
                float2 v1 = {acc[fm][fn][2] * alpha, acc[fm][fn][3] * alpha};
                *(float2*)(Cf + (long)row * N + col) = v0;
                *(float2*)(Cf + (long)(row + 8) * N + col) = v1;
            } else {
                __half2 v0 = __floats2half2_rn(acc[fm][fn][0], acc[fm][fn][1]);
                __half2 v1 = __floats2half2_rn(acc[fm][fn][2], acc[fm][fn][3]);
                *(__half2*)(Ch + (long)row * N + col) = v0;
                *(__half2*)(Ch + (long)(row + 8) * N + col) = v1;
            }
        }
    }
}

// ---------------------------------------------------------------------------
// fp32 -> fp16 conversion (float4 grid-stride)
// ---------------------------------------------------------------------------
__global__ void tofp16(const float* __restrict__ x, fp16* __restrict__ y, long n4)
{
    long i = blockIdx.x * (long)blockDim.x + threadIdx.x;
    const long stride = (long)gridDim.x * blockDim.x;
    for (; i < n4; i += stride) {
        const float4 v = ((const float4*)x)[i];
        __half2 a = __floats2half2_rn(v.x, v.y);
        __half2 b = __floats2half2_rn(v.z, v.w);
        uint2 o = {*(uint32_t*)&a, *(uint32_t*)&b};
        ((uint2*)y)[i] = o;
    }
}

// ---------------------------------------------------------------------------
// H [b,l,d] fp32 -> Ht [b,d,l] fp16  (32x32 smem tile transpose)
// grid (DH/32, L/32, B), 256 threads
// ---------------------------------------------------------------------------
__global__ void __launch_bounds__(256)
transpose_h(const float* __restrict__ H, fp16* __restrict__ Ht)
{
    __shared__ float t[32][33];
    const int b = blockIdx.z;
    const int d0 = blockIdx.x * 32;
    const int l0 = blockIdx.y * 32;
    const int tx = threadIdx.x & 31;
    const int ty = threadIdx.x >> 5;   // 0..7
#pragma unroll
    for (int i = 0; i < 4; i++) {
        const int ll = ty + i * 8;
        t[ll][tx] = H[((long)b * L_ + (l0 + ll)) * DH + d0 + tx];
    }
    __syncthreads();
#pragma unroll
    for (int i = 0; i < 4; i++) {
        const int dd = ty + i * 8;
        Ht[((long)b * DH + (d0 + dd)) * L_ + l0 + tx] = __float2half_rn(t[tx][dd]);
    }
}

// ---------------------------------------------------------------------------
// Row softmax over L_=2048 (fp32 logits in, fp16 probs out).
// One CTA (256 threads) per row.
// ---------------------------------------------------------------------------
__global__ void __launch_bounds__(256)
softmax_rows(const float* __restrict__ S, fp16* __restrict__ Sf)
{
    const float* p = S + (long)blockIdx.x * L_;
    const int tid = threadIdx.x;

    float2 v[4];
    float m = -CUDART_INF_F;
#pragma unroll
    for (int i = 0; i < 4; i++) {
        v[i] = ((const float2*)p)[i * 256 + tid];
        m = fmaxf(m, fmaxf(v[i].x, v[i].y));
    }

    __shared__ float red[8];
#pragma unroll
    for (int o = 16; o > 0; o >>= 1)
        m = fmaxf(m, __shfl_xor_sync(0xffffffffu, m, o));
    if ((tid & 31) == 0) red[tid >> 5] = m;
    __syncthreads();
    m = red[0];
#pragma unroll
    for (int i = 1; i < 8; i++) m = fmaxf(m, red[i]);

    float s = 0.0f;
#pragma unroll
    for (int i = 0; i < 4; i++) {
        v[i].x = __expf(v[i].x - m);
        v[i].y = __expf(v[i].y - m);
        s += v[i].x + v[i].y;
    }
#pragma unroll
    for (int o = 16; o > 0; o >>= 1)
        s += __shfl_xor_sync(0xffffffffu, s, o);
    __syncthreads();
    if ((tid & 31) == 0) red[tid >> 5] = s;
    __syncthreads();
    s = red[0];
#pragma unroll
    for (int i = 1; i < 8; i++) s += red[i];

    const float inv = 1.0f / s;
    fp16* o = Sf + (long)blockIdx.x * L_;
#pragma unroll
    for (int i = 0; i < 4; i++)
        ((__half2*)o)[i * 256 + tid] = __floats2half2_rn(v[i].x * inv, v[i].y * inv);
}

// ---------------------------------------------------------------------------
// Launch (graph-capturable, allocation-free).
// ---------------------------------------------------------------------------
extern "C" void kernel_launch(void* const* d_in, const int* in_sizes, int n_in,
                              void* d_out, int out_size)
{
    const float* H  = (const float*)d_in[0];  // [B, L, DH]
    const float* G  = (const float*)d_in[1];  // [B, T, DG]
    const float* Wq = (const float*)d_in[2];  // [P, DG]
    const float* Wk = (const float*)d_in[3];  // [P, DH]
    float* Z = (float*)d_out;                 // [B, T, DH]

    fp16 *Hf, *Htf, *Gf, *Wqf, *Wkf, *Kf, *Qf, *Sf;
    float* S;
    cudaGetSymbolAddress((void**)&Hf,  g_Hf);
    cudaGetSymbolAddress((void**)&Htf, g_Htf);
    cudaGetSymbolAddress((void**)&Gf,  g_Gf);
    cudaGetSymbolAddress((void**)&Wqf, g_Wqf);
    cudaGetSymbolAddress((void**)&Wkf, g_Wkf);
    cudaGetSymbolAddress((void**)&Kf,  g_Kf);
    cudaGetSymbolAddress((void**)&Qf,  g_Qf);
    cudaGetSymbolAddress((void**)&Sf,  g_Sf);
    cudaGetSymbolAddress((void**)&S,   g_S);

    cudaFuncSetAttribute(gemm_fp16<0>, cudaFuncAttributeMaxDynamicSharedMemorySize, SMEM_BYTES);
    cudaFuncSetAttribute(gemm_fp16<1>, cudaFuncAttributeMaxDynamicSharedMemorySize, SMEM_BYTES);

    dim3 blk(256);

    // input conversions
    tofp16<<<2048, blk>>>(H,  Hf,  (long)B_ * L_ * DH / 4);
    tofp16<<<1024, blk>>>(G,  Gf,  (long)B_ * T_ * DG / 4);
    tofp16<<<128,  blk>>>(Wq, Wqf, (long)P_ * DG / 4);
    tofp16<<<128,  blk>>>(Wk, Wkf, (long)P_ * DH / 4);
    transpose_h<<<dim3(DH / 32, L_ / 32, B_), blk>>>(H, Htf);

    // 1) K = H @ Wk^T   M=32768, N=256, K=1280  -> fp16
    gemm_fp16<1><<<dim3(P_ / BN, (B_ * L_) / BM, 1), blk, SMEM_BYTES>>>(
        Hf, Wkf, nullptr, Kf, DH, P_, 0, 0, 0, 1.0f);

    // 2) Q = G @ Wq^T   M=8192, N=256, K=768    -> fp16
    gemm_fp16<1><<<dim3(P_ / BN, (B_ * T_) / BM, 1), blk, SMEM_BYTES>>>(
        Gf, Wqf, nullptr, Qf, DG, P_, 0, 0, 0, 1.0f);

    // 3) S = scale * Q @ K^T   per b: M=512, N=2048, K=256 -> fp32
    gemm_fp16<0><<<dim3(L_ / BN, T_ / BM, B_), blk, SMEM_BYTES>>>(
        Qf, Kf, S, nullptr, P_, L_,
        (long)T_ * P_, (long)L_ * P_, (long)T_ * L_, SCALE_);

    // 4) softmax -> fp16 probs
    softmax_rows<<<B_ * T_, blk>>>(S, Sf);

    // 5) Z = A @ H   per b: M=512, N=1280, K=2048 -> fp32 out
    gemm_fp16<0><<<dim3(DH / BN, T_ / BM, B_), blk, SMEM_BYTES>>>(
        Sf, Htf, Z, nullptr, L_, DH,
        (long)T_ * L_, (long)DH * L_, (long)T_ * DH, 1.0f);
}

// round 7
// speedup vs baseline: 6.5544x; 1.1467x over previous
#include <cuda_runtime.h>
#include <cuda_fp16.h>
#include <math_constants.h>
#include <cstdint>

// Problem dims (fixed by the reference)
#define B_  16
#define L_  2048
#define DH  1280
#define T_  512
#define DG  768
#define P_  256
#define SCALE_ 0.0625f   // 256^-0.5

typedef __half fp16;

// ---------------- device-global scratch (allocation-free rule) --------------
__device__ __align__(16) fp16 g_Hf [(long)B_ * L_ * DH];   // H  fp16 [b,l,d]
__device__ __align__(16) fp16 g_Gf [(long)B_ * T_ * DG];
__device__ __align__(16) fp16 g_Wqf[P_ * DG];
__device__ __align__(16) fp16 g_Wkf[P_ * DH];
__device__ __align__(16) fp16 g_Kf [(long)B_ * L_ * P_];   // K fp16
__device__ __align__(16) fp16 g_Qf [(long)B_ * T_ * P_];   // Q fp16
__device__ __align__(16) float g_S [(long)B_ * T_ * L_];   // logits fp32
__device__ __align__(16) fp16 g_Sf [(long)B_ * T_ * L_];   // probs fp16

// ---------------------------------------------------------------------------
// fp16 tensor-core GEMM, cp.async double-buffered, 2 CTAs/SM.
//   TRANS_B = true : C = alpha * A[M,K] @ B[N,K]^T   (NT; both K-major)
//   TRANS_B = false: C = alpha * A[M,K] @ B[K,N]     (NN; B staged row-major,
//                     consumed via ldmatrix.trans)
//   fp32 accumulate. EPI=0: fp32 C (alpha applied). EPI=1: fp16 C.
// BM=BN=128, BK=64, 256 threads = 8 warps (2M x 4N), warp tile 64x32.
// ---------------------------------------------------------------------------
#define BM 128
#define BN 128
#define BK 64
#define SK 72                      // NT row stride (halves)
#define BNP 136                    // NN B row stride (halves), 272B
#define STAGE_A (BM * SK)          // 9216 halves
#define STAGE_B_NT (BN * SK)       // 9216
#define STAGE_B_NN (BK * BNP)      // 8704
#define BUF_NT (STAGE_A + STAGE_B_NT)
#define BUF_NN (STAGE_A + STAGE_B_NN)
#define SMEM_MAX (2 * BUF_NT * 2)  // 73728 B

__device__ __forceinline__ uint32_t smem_a32(const void* p) {
    return (uint32_t)__cvta_generic_to_shared(p);
}

__device__ __forceinline__ void cpa16(uint32_t d, const void* s) {
    asm volatile("cp.async.cg.shared.global [%0], [%1], 16;" :: "r"(d), "l"(s));
}
__device__ __forceinline__ void cpa_commit() {
    asm volatile("cp.async.commit_group;" ::: "memory");
}
__device__ __forceinline__ void cpa_wait0() {
    asm volatile("cp.async.wait_group 0;" ::: "memory");
}

__device__ __forceinline__ void ldm4(uint32_t a, uint32_t& r0, uint32_t& r1,
                                     uint32_t& r2, uint32_t& r3) {
    asm volatile("ldmatrix.sync.aligned.m8n8.x4.shared.b16 {%0,%1,%2,%3}, [%4];\n"
                 : "=r"(r0), "=r"(r1), "=r"(r2), "=r"(r3) : "r"(a));
}
__device__ __forceinline__ void ldm4t(uint32_t a, uint32_t& r0, uint32_t& r1,
                                      uint32_t& r2, uint32_t& r3) {
    asm volatile("ldmatrix.sync.aligned.m8n8.x4.trans.shared.b16 {%0,%1,%2,%3}, [%4];\n"
                 : "=r"(r0), "=r"(r1), "=r"(r2), "=r"(r3) : "r"(a));
}

__device__ __forceinline__ void mma16816(float* c, const uint32_t* a,
                                         uint32_t b0, uint32_t b1) {
    asm volatile(
        "mma.sync.aligned.m16n8k16.row.col.f32.f16.f16.f32 "
        "{%0,%1,%2,%3}, {%4,%5,%6,%7}, {%8,%9}, {%0,%1,%2,%3};\n"
        : "+f"(c[0]), "+f"(c[1]), "+f"(c[2]), "+f"(c[3])
        : "r"(a[0]), "r"(a[1]), "r"(a[2]), "r"(a[3]), "r"(b0), "r"(b1));
}

template <int EPI, bool TRANS_B>
__global__ void __launch_bounds__(256, 2)
gemm_fp16(const fp16* __restrict__ A, const fp16* __restrict__ Bm,
          float* __restrict__ Cf, fp16* __restrict__ Ch,
          int K, int N, long sA, long sB, long sC, float alpha)
{
    constexpr int BUF = TRANS_B ? BUF_NT : BUF_NN;
    extern __shared__ fp16 sm[];   // [2][BUF]

    const long bz = blockIdx.z;
    A  += bz * sA;
    Bm += bz * sB;
    const int m0 = blockIdx.y * BM;
    const int n0 = blockIdx.x * BN;

    const int tid  = threadIdx.x;
    const int lane = tid & 31;
    const int wid  = tid >> 5;
    const int wm = (wid & 1) * 64;    // warp M offset
    const int wn = (wid >> 1) * 32;   // warp N offset

    // A staging indices: [128 rows][64 halves] = 8 16B-chunks per row
    const int srow = tid >> 3;        // 0..31 (+ i*32)
    const int scc  = (tid & 7) * 8;   // half offset within row

    float acc[4][4][4];
#pragma unroll
    for (int i = 0; i < 4; i++)
#pragma unroll
        for (int j = 0; j < 4; j++)
#pragma unroll
            for (int q = 0; q < 4; q++) acc[i][j][q] = 0.0f;

    const uint32_t smBase = smem_a32(sm);
    // A ldmatrix base
    const uint32_t aBase = smBase +
        (uint32_t)(((wm + (lane & 15)) * SK + (lane >> 4) * 8) * 2);
    // NT B ldmatrix base
    const int bg = lane >> 3, br = lane & 7;
    const uint32_t bBaseNT = smBase + (uint32_t)(STAGE_A * 2) +
        (uint32_t)(((wn + (bg >> 1) * 8 + br) * SK + (bg & 1) * 8) * 2);
    // NN B ldmatrix.trans base: reg r(bg): k rows (bg&1)*8+br, n offset (bg>>1)*8
    const uint32_t bBaseNN = smBase + (uint32_t)(STAGE_A * 2) +
        (uint32_t)((((bg & 1) * 8 + br) * BNP + wn + (bg >> 1) * 8) * 2);

    const int nk = K / BK;

    // ---- cp.async staging of k-tile kt into buffer buf ----
    auto stage = [&](int kt, int buf) {
        const long k0 = (long)kt * BK;
        const uint32_t dA = smBase + (uint32_t)(buf * BUF * 2);
#pragma unroll
        for (int i = 0; i < 4; i++)
            cpa16(dA + (uint32_t)(((srow + i * 32) * SK + scc) * 2),
                  A + (long)(m0 + srow + i * 32) * K + k0 + scc);
        const uint32_t dB = dA + (uint32_t)(STAGE_A * 2);
        if (TRANS_B) {
#pragma unroll
            for (int i = 0; i < 4; i++)
                cpa16(dB + (uint32_t)(((srow + i * 32) * SK + scc) * 2),
                      Bm + (long)(n0 + srow + i * 32) * K + k0 + scc);
        } else {
            // B tile [BK=64 rows][128 halves] = 64*16 = 1024 chunks, 4/thread
#pragma unroll
            for (int i = 0; i < 4; i++) {
                const int ch = tid + i * 256;
                const int kr = ch >> 4;          // 0..63
                const int nc = (ch & 15) * 8;    // 0..120
                cpa16(dB + (uint32_t)((kr * BNP + nc) * 2),
                      Bm + (k0 + kr) * (long)N + n0 + nc);
            }
        }
    };

    stage(0, 0);
    cpa_commit();
    cpa_wait0();
    __syncthreads();

    for (int kt = 0; kt < nk; kt++) {
        const int cur = kt & 1;
        const bool more = (kt + 1 < nk);
        if (more) {
            stage(kt + 1, 1 - cur);
            cpa_commit();
        }

        const uint32_t bufOff = (uint32_t)(cur * (BUF * 2));
#pragma unroll
        for (int ks = 0; ks < 4; ks++) {
            uint32_t af[4][4], bf[2][4];
#pragma unroll
            for (int fm = 0; fm < 4; fm++)
                ldm4(aBase + bufOff + (uint32_t)(fm * (16 * SK * 2) + ks * 32),
                     af[fm][0], af[fm][1], af[fm][2], af[fm][3]);
            if (TRANS_B) {
#pragma unroll
                for (int f2 = 0; f2 < 2; f2++)
                    ldm4(bBaseNT + bufOff + (uint32_t)(f2 * (16 * SK * 2) + ks * 32),
                         bf[f2][0], bf[f2][1], bf[f2][2], bf[f2][3]);
            } else {
#pragma unroll
                for (int f2 = 0; f2 < 2; f2++)
                    ldm4t(bBaseNN + bufOff +
                              (uint32_t)(ks * (16 * BNP * 2) + f2 * 32),
                          bf[f2][0], bf[f2][1], bf[f2][2], bf[f2][3]);
            }
#pragma unroll
            for (int fm = 0; fm < 4; fm++)
#pragma unroll
                for (int fn = 0; fn < 4; fn++)
                    mma16816(acc[fm][fn], af[fm],
                             bf[fn >> 1][(fn & 1) * 2],
                             bf[fn >> 1][(fn & 1) * 2 + 1]);
        }

        if (more) cpa_wait0();
        __syncthreads();
    }

    // ---- epilogue ----
    const int er = lane >> 2, ec = (lane & 3) * 2;
    if (EPI == 0) Cf += bz * sC; else Ch += bz * sC;
#pragma unroll
    for (int fm = 0; fm < 4; fm++) {
#pragma unroll
        for (int fn = 0; fn < 4; fn++) {
            const int row = m0 + wm + fm * 16 + er;
            const int col = n0 + wn + fn * 8 + ec;
            if (EPI == 0) {
                float2 v0 = {acc[fm][fn][0] * alpha, acc[fm][fn][1] * alpha};
                float2 v1 = {acc[fm][fn][2] * alpha, acc[fm][fn][3] * alpha};
                *(float2*)(Cf + (long)row * N + col) = v0;
                *(float2*)(Cf + (long)(row + 8) * N + col) = v1;
            } else {
                __half2 v0 = __floats2half2_rn(acc[fm][fn][0], acc[fm][fn][1]);
                __half2 v1 = __floats2half2_rn(acc[fm][fn][2], acc[fm][fn][3]);
                *(__half2*)(Ch + (long)row * N + col) = v0;
                *(__half2*)(Ch + (long)(row + 8) * N + col) = v1;
            }
        }
    }
}

// ---------------------------------------------------------------------------
// fp32 -> fp16 conversion (float4 grid-stride)
// ---------------------------------------------------------------------------
__global__ void tofp16(const float* __restrict__ x, fp16* __restrict__ y, long n4)
{
    long i = blockIdx.x * (long)blockDim.x + threadIdx.x;
    const long stride = (long)gridDim.x * blockDim.x;
    for (; i < n4; i += stride) {
        const float4 v = ((const float4*)x)[i];
        __half2 a = __floats2half2_rn(v.x, v.y);
        __half2 b = __floats2half2_rn(v.z, v.w);
        uint2 o = {*(uint32_t*)&a, *(uint32_t*)&b};
        ((uint2*)y)[i] = o;
    }
}

// ---------------------------------------------------------------------------
// Row softmax over L_=2048 (fp32 logits in, fp16 probs out).
// ---------------------------------------------------------------------------
__global__ void __launch_bounds__(256)
softmax_rows(const float* __restrict__ S, fp16* __restrict__ Sf)
{
    const float* p = S + (long)blockIdx.x * L_;
    const int tid = threadIdx.x;

    float2 v[4];
    float m = -CUDART_INF_F;
#pragma unroll
    for (int i = 0; i < 4; i++) {
        v[i] = ((const float2*)p)[i * 256 + tid];
        m = fmaxf(m, fmaxf(v[i].x, v[i].y));
    }

    __shared__ float red[8];
#pragma unroll
    for (int o = 16; o > 0; o >>= 1)
        m = fmaxf(m, __shfl_xor_sync(0xffffffffu, m, o));
    if ((tid & 31) == 0) red[tid >> 5] = m;
    __syncthreads();
    m = red[0];
#pragma unroll
    for (int i = 1; i < 8; i++) m = fmaxf(m, red[i]);

    float s = 0.0f;
#pragma unroll
    for (int i = 0; i < 4; i++) {
        v[i].x = __expf(v[i].x - m);
        v[i].y = __expf(v[i].y - m);
        s += v[i].x + v[i].y;
    }
#pragma unroll
    for (int o = 16; o > 0; o >>= 1)
        s += __shfl_xor_sync(0xffffffffu, s, o);
    __syncthreads();
    if ((tid & 31) == 0) red[tid >> 5] = s;
    __syncthreads();
    s = red[0];
#pragma unroll
    for (int i = 1; i < 8; i++) s += red[i];

    const float inv = 1.0f / s;
    fp16* o = Sf + (long)blockIdx.x * L_;
#pragma unroll
    for (int i = 0; i < 4; i++)
        ((__half2*)o)[i * 256 + tid] = __floats2half2_rn(v[i].x * inv, v[i].y * inv);
}

// ---------------------------------------------------------------------------
// Launch (graph-capturable, allocation-free).
// ---------------------------------------------------------------------------
extern "C" void kernel_launch(void* const* d_in, const int* in_sizes, int n_in,
                              void* d_out, int out_size)
{
    const float* H  = (const float*)d_in[0];  // [B, L, DH]
    const float* G  = (const float*)d_in[1];  // [B, T, DG]
    const float* Wq = (const float*)d_in[2];  // [P, DG]
    const float* Wk = (const float*)d_in[3];  // [P, DH]
    float* Z = (float*)d_out;                 // [B, T, DH]

    fp16 *Hf, *Gf, *Wqf, *Wkf, *Kf, *Qf, *Sf;
    float* S;
    cudaGetSymbolAddress((void**)&Hf,  g_Hf);
    cudaGetSymbolAddress((void**)&Gf,  g_Gf);
    cudaGetSymbolAddress((void**)&Wqf, g_Wqf);
    cudaGetSymbolAddress((void**)&Wkf, g_Wkf);
    cudaGetSymbolAddress((void**)&Kf,  g_Kf);
    cudaGetSymbolAddress((void**)&Qf,  g_Qf);
    cudaGetSymbolAddress((void**)&Sf,  g_Sf);
    cudaGetSymbolAddress((void**)&S,   g_S);

    cudaFuncSetAttribute(gemm_fp16<1, true>,
                         cudaFuncAttributeMaxDynamicSharedMemorySize, SMEM_MAX);
    cudaFuncSetAttribute(gemm_fp16<0, true>,
                         cudaFuncAttributeMaxDynamicSharedMemorySize, SMEM_MAX);
    cudaFuncSetAttribute(gemm_fp16<0, false>,
                         cudaFuncAttributeMaxDynamicSharedMemorySize, SMEM_MAX);

    dim3 blk(256);

    // input conversions
    tofp16<<<2048, blk>>>(H,  Hf,  (long)B_ * L_ * DH / 4);
    tofp16<<<1024, blk>>>(G,  Gf,  (long)B_ * T_ * DG / 4);
    tofp16<<<128,  blk>>>(Wq, Wqf, (long)P_ * DG / 4);
    tofp16<<<128,  blk>>>(Wk, Wkf, (long)P_ * DH / 4);

    // 1) K = H @ Wk^T   M=32768, N=256, K=1280  -> fp16 (NT)
    gemm_fp16<1, true><<<dim3(P_ / BN, (B_ * L_) / BM, 1), blk, 2 * BUF_NT * 2>>>(
        Hf, Wkf, nullptr, Kf, DH, P_, 0, 0, 0, 1.0f);

    // 2) Q = G @ Wq^T   M=8192, N=256, K=768    -> fp16 (NT)
    gemm_fp16<1, true><<<dim3(P_ / BN, (B_ * T_) / BM, 1), blk, 2 * BUF_NT * 2>>>(
        Gf, Wqf, nullptr, Qf, DG, P_, 0, 0, 0, 1.0f);

    // 3) S = scale * Q @ K^T   per b: M=512, N=2048, K=256 -> fp32 (NT)
    gemm_fp16<0, true><<<dim3(L_ / BN, T_ / BM, B_), blk, 2 * BUF_NT * 2>>>(
        Qf, Kf, S, nullptr, P_, L_,
        (long)T_ * P_, (long)L_ * P_, (long)T_ * L_, SCALE_);

    // 4) softmax -> fp16 probs
    softmax_rows<<<B_ * T_, blk>>>(S, Sf);

    // 5) Z = A @ H   per b: M=512, N=1280, K=2048 -> fp32 (NN, B=Hf direct)
    gemm_fp16<0, false><<<dim3(DH / BN, T_ / BM, B_), blk, 2 * BUF_NN * 2>>>(
        Sf, Hf, Z, nullptr, L_, DH,
        (long)T_ * L_, (long)L_ * DH, (long)T_ * DH, 1.0f);
}